// round 4
// baseline (speedup 1.0000x reference)
#include <cuda_runtime.h>
#include <math.h>
#include <stdint.h>

// ---------------------------------------------------------------------------
// ToRGB: out = tanh( (x * s[b]) @ k2d + bias ),  s = (w@affine_w + affine_b)/sqrt(512)
// Fold: keff[b,c,o] = s[b,c] * k2d[c,o]
// Main kernel: TMA bulk-copy pipeline (2-stage smem ring) + warp-per-pixel FMA.
// ---------------------------------------------------------------------------

#define B_    8
#define CIN   512
#define WDIM  128
#define COUT  4
#define PIX   (128*128)
#define INV_SQRT_CIN 0.04419417382415922f

// folded per-batch kernel, PERMUTED: idx = (i*4 + j)*32 + lane, c = lane*4 + j + i*128
__device__ float4 g_keff[B_ * CIN];

// ---------------------------------------------------------------------------
// Prologue (unchanged): grid=(8,4), block=(128,4).
// ---------------------------------------------------------------------------
__global__ void build_keff_kernel(const float* __restrict__ w,
                                  const float* __restrict__ affine_w,
                                  const float* __restrict__ affine_b,
                                  const float* __restrict__ k2d)
{
    const int b  = blockIdx.x;
    const int c  = blockIdx.y * 128 + threadIdx.x;
    const int js = threadIdx.y;

    __shared__ float ws[WDIM];
    __shared__ float part[3][128];

    const int tid = threadIdx.y * 128 + threadIdx.x;
    if (tid < WDIM) ws[tid] = w[b * WDIM + tid];
    __syncthreads();

    float s = 0.f;
    const int j0 = js * 32;
    #pragma unroll 8
    for (int j = j0; j < j0 + 32; j++)
        s = fmaf(ws[j], affine_w[j * CIN + c], s);

    if (js > 0) part[js - 1][threadIdx.x] = s;
    __syncthreads();

    if (js == 0) {
        s += part[0][threadIdx.x] + part[1][threadIdx.x] + part[2][threadIdx.x];
        s = (s + affine_b[c]) * INV_SQRT_CIN;
        float4 kk = *reinterpret_cast<const float4*>(k2d + c * COUT);
        float4 o;
        o.x = s * kk.x; o.y = s * kk.y; o.z = s * kk.z; o.w = s * kk.w;
        const int i = c >> 7, r = c & 127, lane = r >> 2, jj = r & 3;
        g_keff[b * CIN + (i * 4 + jj) * 32 + lane] = o;
    }
}

// ---------------------------------------------------------------------------
// PTX helpers
// ---------------------------------------------------------------------------
__device__ __forceinline__ uint32_t smem_u32(const void* p) {
    uint32_t a;
    asm("{ .reg .u64 t; cvta.to.shared.u64 t, %1; cvt.u32.u64 %0, t; }"
        : "=r"(a) : "l"(p));
    return a;
}
__device__ __forceinline__ void mbar_init(uint32_t bar, uint32_t cnt) {
    asm volatile("mbarrier.init.shared.b64 [%0], %1;" :: "r"(bar), "r"(cnt) : "memory");
}
__device__ __forceinline__ void mbar_expect_tx(uint32_t bar, uint32_t bytes) {
    asm volatile("mbarrier.arrive.expect_tx.shared.b64 _, [%0], %1;"
                 :: "r"(bar), "r"(bytes) : "memory");
}
__device__ __forceinline__ void mbar_arrive(uint32_t bar) {
    asm volatile("mbarrier.arrive.shared.b64 _, [%0];" :: "r"(bar) : "memory");
}
__device__ __forceinline__ void mbar_wait(uint32_t bar, uint32_t parity) {
    asm volatile(
        "{\n\t"
        ".reg .pred P;\n\t"
        "LAB_WAIT_%=:\n\t"
        "mbarrier.try_wait.parity.acquire.cta.shared::cta.b64 P, [%0], %1, 0x989680;\n\t"
        "@P bra.uni LAB_DONE_%=;\n\t"
        "bra.uni LAB_WAIT_%=;\n\t"
        "LAB_DONE_%=:\n\t"
        "}"
        :: "r"(bar), "r"(parity) : "memory");
}
__device__ __forceinline__ void bulk_ld(uint32_t dst_smem, const void* src_gmem,
                                        uint32_t bytes, uint32_t bar) {
    asm volatile(
        "cp.async.bulk.shared::cluster.global.mbarrier::complete_tx::bytes "
        "[%0], [%1], %2, [%3];"
        :: "r"(dst_smem), "l"(src_gmem), "r"(bytes), "r"(bar) : "memory");
}

// packed pair reduction: two independent sums, one shuffle
__device__ __forceinline__ float pairstep(float a, float b, bool lo, int off)
{
    float send = lo ? b : a;
    float recv = __shfl_xor_sync(0xffffffffu, send, off);
    return (lo ? a : b) + recv;
}

// ---------------------------------------------------------------------------
// Main: grid=(256, 8), block=256 (8 warps). 64 px per CTA = 8 tiles of 8 px.
// 2-stage 16KB smem ring filled by cp.async.bulk, issued 2 tiles ahead.
// ---------------------------------------------------------------------------
#define BLOCKS_PER_BATCH 256
#define PIX_PER_BLOCK    64
#define TILE_PX          8
#define TILE_BYTES       (TILE_PX * CIN * 4)      // 16384
#define TILES            (PIX_PER_BLOCK / TILE_PX) // 8
#define STAGES           2

__global__ void __launch_bounds__(256, 5)
torgb_main_kernel(const float* __restrict__ x,
                  const float* __restrict__ bias,
                  float* __restrict__ out)
{
    __shared__ __align__(128) float4 tiles[STAGES][TILE_PX * CIN / 4]; // 2 x 16KB
    __shared__ __align__(128) float4 kws[CIN];                          // 8KB
    __shared__ __align__(16)  uint64_t mbars[2 * STAGES];  // full[0..1], empty[0..1]

    const int b    = blockIdx.y;
    const int tid  = threadIdx.x;
    const int warp = tid >> 5;
    const int lane = tid & 31;

    const uint32_t full0  = smem_u32(&mbars[0]);
    const uint32_t empty0 = smem_u32(&mbars[STAGES]);

    // ---- init barriers + keff smem ----
    if (tid == 0) {
        #pragma unroll
        for (int s = 0; s < STAGES; s++) {
            mbar_init(full0  + 8u * s, 1);   // completed by expect_tx bytes
            mbar_init(empty0 + 8u * s, 8);   // one arrive per warp
        }
    }
    {
        const float4* gk = g_keff + b * CIN;
        kws[tid]       = gk[tid];
        kws[tid + 256] = gk[tid + 256];
    }
    __syncthreads();

    const long long pix0 = (long long)b * PIX + blockIdx.x * PIX_PER_BLOCK;
    const char* xsrc = (const char*)(x + pix0 * CIN);
    float*      obase = out + pix0 * COUT;

    // ---- prologue: issue tiles 0 and 1 ----
    if (tid == 0) {
        #pragma unroll
        for (int t = 0; t < STAGES; t++) {
            mbar_expect_tx(full0 + 8u * t, TILE_BYTES);
            bulk_ld(smem_u32(&tiles[t][0]), xsrc + (long long)t * TILE_BYTES,
                    TILE_BYTES, full0 + 8u * t);
        }
    }

    const float4* kwl = kws + lane;
    const float mybias = bias[lane >> 3];       // storer lanes: 0,8,16,24 -> o=0..3
    const bool  storer = (lane & 7) == 0;
    const int   o_idx  = lane >> 3;
    const bool  lo16 = (lane & 16) == 0;
    const bool  lo8  = (lane & 8)  == 0;

    #pragma unroll 1
    for (int t = 0; t < TILES; t++) {
        const int s = t & 1;
        const uint32_t pf = (t >> 1) & 1;

        mbar_wait(full0 + 8u * s, pf);

        // warp computes pixel (t*8 + warp); row = warp*2KB in tile
        const float4* row = &tiles[s][warp * (CIN / 4)] + lane;   // lane*16B

        float v0 = 0.f, v1 = 0.f, v2 = 0.f, v3 = 0.f;
        #pragma unroll
        for (int i = 0; i < 4; i++) {
            const float4 a = row[i * 32];             // LDS.128, conflict-free
            const float av[4] = {a.x, a.y, a.z, a.w};
            #pragma unroll
            for (int j = 0; j < 4; j++) {
                const float4 k = kwl[(i * 4 + j) * 32];
                v0 = fmaf(av[j], k.x, v0);
                v1 = fmaf(av[j], k.y, v1);
                v2 = fmaf(av[j], k.z, v2);
                v3 = fmaf(av[j], k.w, v3);
            }
        }

        // packed butterfly: 4 sums in 6 shuffles.
        // after step16: v0/v2 chains split on bit4; after step8: bit3 splits v0/v1.
        float r0 = pairstep(v0, v2, lo16, 16);
        float r1 = pairstep(v1, v3, lo16, 16);
        float u  = pairstep(r0, r1, lo8, 8);
        u += __shfl_xor_sync(0xffffffffu, u, 4);
        u += __shfl_xor_sync(0xffffffffu, u, 2);
        u += __shfl_xor_sync(0xffffffffu, u, 1);
        // lane 0->o0, 8->o1, 16->o2, 24->o3

        // release the stage
        if (lane == 0) mbar_arrive(empty0 + 8u * s);

        if (storer)
            obase[(long long)(t * TILE_PX + warp) * COUT + o_idx] = tanhf(u + mybias);

        // producer: refill this stage with tile t+2 once all 8 warps released it
        if (tid == 0 && t < TILES - STAGES) {
            mbar_wait(empty0 + 8u * s, pf);
            mbar_expect_tx(full0 + 8u * s, TILE_BYTES);
            bulk_ld(smem_u32(&tiles[s][0]), xsrc + (long long)(t + STAGES) * TILE_BYTES,
                    TILE_BYTES, full0 + 8u * s);
        }
    }
}

// ---------------------------------------------------------------------------
// inputs: x[8,128,128,512], w[8,128], affine_w[128,512], affine_b[512],
//         kernel[1,1,512,4], bias[4]  -> out[8,128,128,4] f32
// ---------------------------------------------------------------------------
extern "C" void kernel_launch(void* const* d_in, const int* in_sizes, int n_in,
                              void* d_out, int out_size)
{
    const float* x        = (const float*)d_in[0];
    const float* w        = (const float*)d_in[1];
    const float* affine_w = (const float*)d_in[2];
    const float* affine_b = (const float*)d_in[3];
    const float* k2d      = (const float*)d_in[4];
    const float* bias     = (const float*)d_in[5];
    float*       out      = (float*)d_out;

    dim3 pgrid(B_, 4), pblock(128, 4);
    build_keff_kernel<<<pgrid, pblock>>>(w, affine_w, affine_b, k2d);

    dim3 grid(BLOCKS_PER_BATCH, B_);
    torgb_main_kernel<<<grid, 256>>>(x, bias, out);
}

// round 5
// speedup vs baseline: 1.2305x; 1.2305x over previous
#include <cuda_runtime.h>
#include <math.h>

// ---------------------------------------------------------------------------
// ToRGB: out = tanh( (x * s[b]) @ k2d + bias ),  s = (w@affine_w + affine_b)/sqrt(512)
// Fold: keff[b,c,o] = s[b,c] * k2d[c,o]
// Main: direct-LDG streaming, software-pipelined 1 pixel/iter, 5 CTAs/SM.
// ---------------------------------------------------------------------------

#define B_    8
#define CIN   512
#define WDIM  128
#define COUT  4
#define PIX   (128*128)
#define INV_SQRT_CIN 0.04419417382415922f

// folded per-batch kernel, PERMUTED: idx = (i*4 + j)*32 + lane, c = lane*4 + j + i*128
__device__ float4 g_keff[B_ * CIN];

// ---------------------------------------------------------------------------
// Prologue: grid=(8,4), block=(128,4). Split 128-dot over 4 j-slices.
// ---------------------------------------------------------------------------
__global__ void build_keff_kernel(const float* __restrict__ w,
                                  const float* __restrict__ affine_w,
                                  const float* __restrict__ affine_b,
                                  const float* __restrict__ k2d)
{
    const int b  = blockIdx.x;
    const int c  = blockIdx.y * 128 + threadIdx.x;
    const int js = threadIdx.y;

    __shared__ float ws[WDIM];
    __shared__ float part[3][128];

    const int tid = threadIdx.y * 128 + threadIdx.x;
    if (tid < WDIM) ws[tid] = w[b * WDIM + tid];
    __syncthreads();

    float s = 0.f;
    const int j0 = js * 32;
    #pragma unroll 8
    for (int j = j0; j < j0 + 32; j++)
        s = fmaf(ws[j], affine_w[j * CIN + c], s);

    if (js > 0) part[js - 1][threadIdx.x] = s;
    __syncthreads();

    if (js == 0) {
        s += part[0][threadIdx.x] + part[1][threadIdx.x] + part[2][threadIdx.x];
        s = (s + affine_b[c]) * INV_SQRT_CIN;
        float4 kk = *reinterpret_cast<const float4*>(k2d + c * COUT);
        float4 o;
        o.x = s * kk.x; o.y = s * kk.y; o.z = s * kk.z; o.w = s * kk.w;
        const int i = c >> 7, r = c & 127, lane = r >> 2, jj = r & 3;
        g_keff[b * CIN + (i * 4 + jj) * 32 + lane] = o;
    }
}

// packed pair reduction: two independent sums, one shuffle
__device__ __forceinline__ float pairstep(float a, float b, bool lo, int off)
{
    float send = lo ? b : a;
    float recv = __shfl_xor_sync(0xffffffffu, send, off);
    return (lo ? a : b) + recv;
}

// ---------------------------------------------------------------------------
// Main: grid=(256, 8), block=256 (8 warps), 5 CTAs/SM.
// Warp-per-pixel, 8 pixels per warp, next pixel's loads prefetched before
// the reduce chain so DRAM stays busy through shuffles/stores.
// ---------------------------------------------------------------------------
#define BLOCKS_PER_BATCH 256
#define PIX_PER_BLOCK    (PIX / BLOCKS_PER_BATCH)   // 64
#define PIX_PER_WARP     (PIX_PER_BLOCK / 8)        // 8

__global__ void __launch_bounds__(256, 5)
torgb_main_kernel(const float* __restrict__ x,
                  const float* __restrict__ bias,
                  float* __restrict__ out)
{
    const int b    = blockIdx.y;
    const int warp = threadIdx.x >> 5;
    const int lane = threadIdx.x & 31;

    __shared__ float4 kws[CIN];   // 8 KB

    {
        const float4* gk = g_keff + b * CIN;
        kws[threadIdx.x]       = gk[threadIdx.x];
        kws[threadIdx.x + 256] = gk[threadIdx.x + 256];
    }
    __syncthreads();

    const float4* kwl = kws + lane;

    // final packed-reduce slots: lanes 0,8,16,24 hold outputs 0..3
    const int   o_idx  = lane >> 3;
    const bool  storer = (lane & 7) == 0;
    const float mybias = bias[o_idx];
    const bool  lo16 = (lane & 16) == 0;
    const bool  lo8  = (lane & 8)  == 0;

    const int pix0 = blockIdx.x * PIX_PER_BLOCK + warp * PIX_PER_WARP;
    // float4-typed base: pixel stride = 128 float4, group stride = 32 float4
    const float4* xp = reinterpret_cast<const float4*>(
                           x + ((long long)(b * PIX + pix0)) * CIN) + lane;
    float* obase = out + ((long long)(b * PIX + pix0)) * COUT + o_idx;

    // prologue load: pixel 0
    float4 a0 = __ldcs(xp + 0 * 32);
    float4 a1 = __ldcs(xp + 1 * 32);
    float4 a2 = __ldcs(xp + 2 * 32);
    float4 a3 = __ldcs(xp + 3 * 32);

    #pragma unroll 1
    for (int p = 0; p < PIX_PER_WARP; p++) {
        // ---- prefetch next pixel BEFORE compute/reduce (keeps DRAM busy) ----
        float4 n0, n1, n2, n3;
        if (p < PIX_PER_WARP - 1) {
            const float4* xn = xp + (p + 1) * 128;
            n0 = __ldcs(xn + 0 * 32);
            n1 = __ldcs(xn + 1 * 32);
            n2 = __ldcs(xn + 2 * 32);
            n3 = __ldcs(xn + 3 * 32);
        }

        // ---- 64 FMA over this lane's 16 channels ----
        float v0 = 0.f, v1 = 0.f, v2 = 0.f, v3 = 0.f;
        {
            const float4 ag[4] = {a0, a1, a2, a3};
            #pragma unroll
            for (int i = 0; i < 4; i++) {
                const float av[4] = {ag[i].x, ag[i].y, ag[i].z, ag[i].w};
                #pragma unroll
                for (int j = 0; j < 4; j++) {
                    const float4 k = kwl[(i * 4 + j) * 32];   // LDS.128
                    v0 = fmaf(av[j], k.x, v0);
                    v1 = fmaf(av[j], k.y, v1);
                    v2 = fmaf(av[j], k.z, v2);
                    v3 = fmaf(av[j], k.w, v3);
                }
            }
        }

        // ---- packed butterfly: 4 sums in 6 shuffles ----
        float r0 = pairstep(v0, v2, lo16, 16);
        float r1 = pairstep(v1, v3, lo16, 16);
        float u  = pairstep(r0, r1, lo8, 8);
        u += __shfl_xor_sync(0xffffffffu, u, 4);
        u += __shfl_xor_sync(0xffffffffu, u, 2);
        u += __shfl_xor_sync(0xffffffffu, u, 1);
        // lanes 0,8,16,24 hold o0..o3

        if (storer)
            obase[(long long)p * COUT] = tanhf(u + mybias);

        a0 = n0; a1 = n1; a2 = n2; a3 = n3;
    }
}

// ---------------------------------------------------------------------------
// inputs: x[8,128,128,512], w[8,128], affine_w[128,512], affine_b[512],
//         kernel[1,1,512,4], bias[4]  -> out[8,128,128,4] f32
// ---------------------------------------------------------------------------
extern "C" void kernel_launch(void* const* d_in, const int* in_sizes, int n_in,
                              void* d_out, int out_size)
{
    const float* x        = (const float*)d_in[0];
    const float* w        = (const float*)d_in[1];
    const float* affine_w = (const float*)d_in[2];
    const float* affine_b = (const float*)d_in[3];
    const float* k2d      = (const float*)d_in[4];
    const float* bias     = (const float*)d_in[5];
    float*       out      = (float*)d_out;

    dim3 pgrid(B_, 4), pblock(128, 4);
    build_keff_kernel<<<pgrid, pblock>>>(w, affine_w, affine_b, k2d);

    dim3 grid(BLOCKS_PER_BATCH, B_);
    torgb_main_kernel<<<grid, 256>>>(x, bias, out);
}

// round 6
// speedup vs baseline: 1.3244x; 1.0763x over previous
#include <cuda_runtime.h>
#include <math.h>

// ---------------------------------------------------------------------------
// ToRGB: out = tanh( (x * s[b]) @ k2d + bias ),  s = (w@affine_w + affine_b)/sqrt(512)
// Fold: keff[b,c,o] = s[b,c] * k2d[c,o]
// Main: R2 compute body (2-px tile, packed 9-shuffle reduce) inside a
// persistent single-wave grid (74 x 8 = 592 CTAs = 148 SMs x 4 CTAs).
// ---------------------------------------------------------------------------

#define B_    8
#define CIN   512
#define WDIM  128
#define COUT  4
#define PIX   (128*128)
#define INV_SQRT_CIN 0.04419417382415922f

#define GRID_X          74          // 74*8 = 592 = 148 SMs * 4 CTAs -> one wave
#define UNIT_PX         16          // 8 warps * 2 px
#define UNITS_PER_BATCH (PIX / UNIT_PX)   // 1024

// folded per-batch kernel, PERMUTED: idx = (i*4 + j)*32 + lane, c = lane*4 + j + i*128
__device__ float4 g_keff[B_ * CIN];

// ---------------------------------------------------------------------------
// Prologue: grid=(8,4), block=(128,4). Split 128-dot over 4 j-slices.
// ---------------------------------------------------------------------------
__global__ void build_keff_kernel(const float* __restrict__ w,
                                  const float* __restrict__ affine_w,
                                  const float* __restrict__ affine_b,
                                  const float* __restrict__ k2d)
{
    const int b  = blockIdx.x;
    const int c  = blockIdx.y * 128 + threadIdx.x;
    const int js = threadIdx.y;

    __shared__ float ws[WDIM];
    __shared__ float part[3][128];

    const int tid = threadIdx.y * 128 + threadIdx.x;
    if (tid < WDIM) ws[tid] = w[b * WDIM + tid];
    __syncthreads();

    float s = 0.f;
    const int j0 = js * 32;
    #pragma unroll 8
    for (int j = j0; j < j0 + 32; j++)
        s = fmaf(ws[j], affine_w[j * CIN + c], s);

    if (js > 0) part[js - 1][threadIdx.x] = s;
    __syncthreads();

    if (js == 0) {
        s += part[0][threadIdx.x] + part[1][threadIdx.x] + part[2][threadIdx.x];
        s = (s + affine_b[c]) * INV_SQRT_CIN;
        float4 kk = *reinterpret_cast<const float4*>(k2d + c * COUT);
        float4 o;
        o.x = s * kk.x; o.y = s * kk.y; o.z = s * kk.z; o.w = s * kk.w;
        const int i = c >> 7, r = c & 127, lane = r >> 2, jj = r & 3;
        g_keff[b * CIN + (i * 4 + jj) * 32 + lane] = o;
    }
}

// packed pair reduction: two independent sums, one shuffle
__device__ __forceinline__ float pairstep(float a, float b, bool lo, int off)
{
    float send = lo ? b : a;
    float recv = __shfl_xor_sync(0xffffffffu, send, off);
    return (lo ? a : b) + recv;
}

// ---------------------------------------------------------------------------
// Main: grid=(74, 8), block=256 (8 warps), 4 CTAs/SM — exactly one wave.
// Each CTA grid-strides over 16-pixel units; warp handles 2 px per unit
// with the proven R2 body.
// ---------------------------------------------------------------------------
__global__ void __launch_bounds__(256, 4)
torgb_main_kernel(const float* __restrict__ x,
                  const float* __restrict__ bias,
                  float* __restrict__ out)
{
    const int b    = blockIdx.y;
    const int warp = threadIdx.x >> 5;
    const int lane = threadIdx.x & 31;

    __shared__ float4 kws[CIN];   // 8 KB

    {
        const float4* gk = g_keff + b * CIN;
        kws[threadIdx.x]       = gk[threadIdx.x];
        kws[threadIdx.x + 256] = gk[threadIdx.x + 256];
    }
    __syncthreads();

    const float4* kwl = kws + lane;

    // final packed-reduce slots (verified in R2):
    // lanes with (lane&3)==0 store pixel p_off=bit4, output o_idx.
    const int   p_off  = (lane >> 4) & 1;
    const int   o_idx  = (((lane >> 2) & 1) << 1) | ((lane >> 3) & 1);
    const bool  storer = (lane & 3) == 0;
    const float mybias = bias[o_idx];
    const bool  lo16 = lane < 16;
    const bool  lo8  = (lane & 8) == 0;
    const bool  lo4  = (lane & 4) == 0;

    // starting pixel for this warp at unit u = blockIdx.x
    const long long px0 = (long long)b * PIX + (long long)blockIdx.x * UNIT_PX + warp * 2;
    const float4* xp = reinterpret_cast<const float4*>(x + px0 * CIN) + lane; // px = 128 float4
    float*        op = out + px0 * COUT + p_off * COUT + o_idx;

    const long long xstep = (long long)GRID_X * UNIT_PX * (CIN / 4); // float4 per u-step
    const long long ostep = (long long)GRID_X * UNIT_PX * COUT;      // floats per u-step

    #pragma unroll 1
    for (int u = blockIdx.x; u < UNITS_PER_BATCH; u += GRID_X) {
        // ---- 2 pixels: 8 independent LDG.128 ----
        float4 a[4], c4[4];
        #pragma unroll
        for (int i = 0; i < 4; i++) a[i]  = __ldcs(xp + i * 32);
        #pragma unroll
        for (int i = 0; i < 4; i++) c4[i] = __ldcs(xp + 128 + i * 32);

        float v0 = 0.f, v1 = 0.f, v2 = 0.f, v3 = 0.f;
        float v4 = 0.f, v5 = 0.f, v6 = 0.f, v7 = 0.f;

        #pragma unroll
        for (int i = 0; i < 4; i++) {
            const float av[4] = {a[i].x,  a[i].y,  a[i].z,  a[i].w};
            const float cv[4] = {c4[i].x, c4[i].y, c4[i].z, c4[i].w};
            #pragma unroll
            for (int j = 0; j < 4; j++) {
                const float4 k = kwl[(i * 4 + j) * 32];   // LDS.128, imm offset
                v0 = fmaf(av[j], k.x, v0);
                v1 = fmaf(av[j], k.y, v1);
                v2 = fmaf(av[j], k.z, v2);
                v3 = fmaf(av[j], k.w, v3);
                v4 = fmaf(cv[j], k.x, v4);
                v5 = fmaf(cv[j], k.y, v5);
                v6 = fmaf(cv[j], k.z, v6);
                v7 = fmaf(cv[j], k.w, v7);
            }
        }

        // ---- packed butterfly: 8 sums in 9 shuffles (R2-verified) ----
        float r0 = pairstep(v0, v4, lo16, 16);
        float r1 = pairstep(v1, v5, lo16, 16);
        float r2 = pairstep(v2, v6, lo16, 16);
        float r3 = pairstep(v3, v7, lo16, 16);

        float s0 = pairstep(r0, r1, lo8, 8);
        float s1 = pairstep(r2, r3, lo8, 8);

        float t  = pairstep(s0, s1, lo4, 4);
        t += __shfl_xor_sync(0xffffffffu, t, 2);
        t += __shfl_xor_sync(0xffffffffu, t, 1);

        if (storer)
            *op = tanhf(t + mybias);

        xp += xstep;
        op += ostep;
    }
}

// ---------------------------------------------------------------------------
// inputs: x[8,128,128,512], w[8,128], affine_w[128,512], affine_b[512],
//         kernel[1,1,512,4], bias[4]  -> out[8,128,128,4] f32
// ---------------------------------------------------------------------------
extern "C" void kernel_launch(void* const* d_in, const int* in_sizes, int n_in,
                              void* d_out, int out_size)
{
    const float* x        = (const float*)d_in[0];
    const float* w        = (const float*)d_in[1];
    const float* affine_w = (const float*)d_in[2];
    const float* affine_b = (const float*)d_in[3];
    const float* k2d      = (const float*)d_in[4];
    const float* bias     = (const float*)d_in[5];
    float*       out      = (float*)d_out;

    dim3 pgrid(B_, 4), pblock(128, 4);
    build_keff_kernel<<<pgrid, pblock>>>(w, affine_w, affine_b, k2d);

    dim3 grid(GRID_X, B_);
    torgb_main_kernel<<<grid, 256>>>(x, bias, out);
}

// round 8
// speedup vs baseline: 1.3424x; 1.0136x over previous
#include <cuda_runtime.h>
#include <math.h>

// ---------------------------------------------------------------------------
// ToRGB: out = tanh( (x * s[b]) @ k2d + bias ),  s = (w@affine_w + affine_b)/sqrt(512)
// Fold: keff[b,c,o] = s[b,c] * k2d[c,o]
// Main: 8-lane-group scheme. Warp = 4 pixels, group of 8 lanes per pixel,
// depth-3 packed reduce, broadcast keff LDS, single-wave persistent grid.
// ---------------------------------------------------------------------------

#define B_    8
#define CIN   512
#define WDIM  128
#define COUT  4
#define PIX   (128*128)
#define INV_SQRT_CIN 0.04419417382415922f

#define GRID_X          74               // 74*8 = 592 = 148 SMs * 4 CTAs
#define UNIT_PX         32               // 8 warps * 4 px
#define UNITS_PER_BATCH (PIX / UNIT_PX)  // 512

// folded per-batch kernel, PERMUTED for the group scheme:
// channel c = i*32 + lg*4 + j  ->  idx = (i*4 + j)*8 + lg   (i<16, j<4, lg<8)
__device__ float4 g_keff[B_ * CIN];

// ---------------------------------------------------------------------------
// Prologue: grid=(8,8), block=(64,8). 64-channel chunks, 8 j-slices of 16.
// ---------------------------------------------------------------------------
__global__ void build_keff_kernel(const float* __restrict__ w,
                                  const float* __restrict__ affine_w,
                                  const float* __restrict__ affine_b,
                                  const float* __restrict__ k2d)
{
    const int b  = blockIdx.x;
    const int c  = blockIdx.y * 64 + threadIdx.x;
    const int js = threadIdx.y;                    // 0..7

    __shared__ float ws[WDIM];
    __shared__ float part[7][64];

    const int tid = threadIdx.y * 64 + threadIdx.x;
    if (tid < WDIM) ws[tid] = w[b * WDIM + tid];
    __syncthreads();

    float s = 0.f;
    const int j0 = js * 16;
    #pragma unroll
    for (int j = j0; j < j0 + 16; j++)
        s = fmaf(ws[j], affine_w[j * CIN + c], s);

    if (js > 0) part[js - 1][threadIdx.x] = s;
    __syncthreads();

    if (js == 0) {
        #pragma unroll
        for (int q = 0; q < 7; q++) s += part[q][threadIdx.x];
        s = (s + affine_b[c]) * INV_SQRT_CIN;
        float4 kk = *reinterpret_cast<const float4*>(k2d + c * COUT);
        float4 o;
        o.x = s * kk.x; o.y = s * kk.y; o.z = s * kk.z; o.w = s * kk.w;
        // group-scheme permutation
        const int i = c >> 5, r = c & 31, lg = r >> 2, jj = r & 3;
        g_keff[b * CIN + (i * 4 + jj) * 8 + lg] = o;
    }
}

// packed pair reduction: two independent sums, one shuffle
__device__ __forceinline__ float pairstep(float a, float b, bool lo, int off)
{
    float send = lo ? b : a;
    float recv = __shfl_xor_sync(0xffffffffu, send, off);
    return (lo ? a : b) + recv;
}

// ---------------------------------------------------------------------------
// Main: grid=(74, 8), block=256 (8 warps), 4 CTAs/SM — one wave.
// Warp: 4 px per unit; group g = lane>>3 owns pixel g; lane covers 64 channels.
// ---------------------------------------------------------------------------
__global__ void __launch_bounds__(256, 4)
torgb_main_kernel(const float* __restrict__ x,
                  const float* __restrict__ bias,
                  float* __restrict__ out)
{
    const int b    = blockIdx.y;
    const int warp = threadIdx.x >> 5;
    const int lane = threadIdx.x & 31;
    const int g    = lane >> 3;
    const int lg   = lane & 7;

    __shared__ float4 kws[CIN];   // 8 KB

    {
        const float4* gk = g_keff + b * CIN;
        kws[threadIdx.x]       = gk[threadIdx.x];
        kws[threadIdx.x + 256] = gk[threadIdx.x + 256];
    }
    __syncthreads();

    const float4* kwl = kws + lg;   // kwl[(i*4+j)*8] : 8 distinct float4, broadcast x4

    // reduce lane mapping (verified): even lanes hold out o = bit2*2 + bit1
    const int   o_idx  = (((lane >> 2) & 1) << 1) | ((lane >> 1) & 1);
    const bool  storer = (lane & 1) == 0;
    const float mybias = bias[o_idx];
    const bool  lo4 = (lane & 4) == 0;
    const bool  lo2 = (lane & 2) == 0;

    // this warp's pixel for its group at unit u = blockIdx.x
    const long long mypx = (long long)b * PIX + (long long)blockIdx.x * UNIT_PX
                         + warp * 4 + g;
    const float4* xp = reinterpret_cast<const float4*>(x + mypx * CIN) + lg;
    float*        op = out + mypx * COUT + o_idx;

    const long long xstep = (long long)GRID_X * UNIT_PX * (CIN / 4);
    const long long ostep = (long long)GRID_X * UNIT_PX * COUT;

    #pragma unroll 1
    for (int u = blockIdx.x; u < UNITS_PER_BATCH; u += GRID_X) {
        float v0 = 0.f, v1 = 0.f, v2 = 0.f, v3 = 0.f;

        // ---- block 0: sweeps 0..7 (8 front-batched LDG.128) ----
        float4 a[8];
        #pragma unroll
        for (int i = 0; i < 8; i++) a[i] = __ldcs(xp + i * 8);
        #pragma unroll
        for (int i = 0; i < 8; i++) {
            const float av[4] = {a[i].x, a[i].y, a[i].z, a[i].w};
            #pragma unroll
            for (int j = 0; j < 4; j++) {
                const float4 k = kwl[(i * 4 + j) * 8];     // broadcast LDS.128
                v0 = fmaf(av[j], k.x, v0);
                v1 = fmaf(av[j], k.y, v1);
                v2 = fmaf(av[j], k.z, v2);
                v3 = fmaf(av[j], k.w, v3);
            }
        }

        // ---- block 1: sweeps 8..15 ----
        #pragma unroll
        for (int i = 0; i < 8; i++) a[i] = __ldcs(xp + (i + 8) * 8);
        #pragma unroll
        for (int i = 0; i < 8; i++) {
            const float av[4] = {a[i].x, a[i].y, a[i].z, a[i].w};
            #pragma unroll
            for (int j = 0; j < 4; j++) {
                const float4 k = kwl[((i + 8) * 4 + j) * 8];
                v0 = fmaf(av[j], k.x, v0);
                v1 = fmaf(av[j], k.y, v1);
                v2 = fmaf(av[j], k.z, v2);
                v3 = fmaf(av[j], k.w, v3);
            }
        }

        // ---- depth-3 packed reduce within 8-lane group (4 shuffles) ----
        float r0 = pairstep(v0, v2, lo4, 4);
        float r1 = pairstep(v1, v3, lo4, 4);
        float t  = pairstep(r0, r1, lo2, 2);
        t += __shfl_xor_sync(0xffffffffu, t, 1);
        // even lanes: o = bit2*2 + bit1 ; 16 storers -> 64B contiguous per warp

        if (storer)
            *op = tanhf(t + mybias);

        xp += xstep;
        op += ostep;
    }
}

// ---------------------------------------------------------------------------
// inputs: x[8,128,128,512], w[8,128], affine_w[128,512], affine_b[512],
//         kernel[1,1,512,4], bias[4]  -> out[8,128,128,4] f32
// ---------------------------------------------------------------------------
extern "C" void kernel_launch(void* const* d_in, const int* in_sizes, int n_in,
                              void* d_out, int out_size)
{
    const float* x        = (const float*)d_in[0];
    const float* w        = (const float*)d_in[1];
    const float* affine_w = (const float*)d_in[2];
    const float* affine_b = (const float*)d_in[3];
    const float* k2d      = (const float*)d_in[4];
    const float* bias     = (const float*)d_in[5];
    float*       out      = (float*)d_out;

    dim3 pgrid(B_, 8), pblock(64, 8);
    build_keff_kernel<<<pgrid, pblock>>>(w, affine_w, affine_b, k2d);

    dim3 grid(GRID_X, B_);
    torgb_main_kernel<<<grid, 256>>>(x, bias, out);
}

// round 9
// speedup vs baseline: 1.3810x; 1.0287x over previous
#include <cuda_runtime.h>
#include <math.h>

// ---------------------------------------------------------------------------
// ToRGB: out = tanh( (x * s[b]) @ k2d + bias ),  s = (w@affine_w + affine_b)/sqrt(512)
// Fold: keff[b,c,o] = s[b,c] * k2d[c,o]
// Main: R6 2-px body with LOOP ROTATION — next unit's loads issue before the
// reduce chain so DRAM stays busy through shuffles/tanh/store.
// ---------------------------------------------------------------------------

#define B_    8
#define CIN   512
#define WDIM  128
#define COUT  4
#define PIX   (128*128)
#define INV_SQRT_CIN 0.04419417382415922f

#define GRID_X          74               // 74*8 = 592 = 148 SMs * 4 CTAs
#define UNIT_PX         16               // 8 warps * 2 px
#define UNITS_PER_BATCH (PIX / UNIT_PX)  // 1024

// folded per-batch kernel, PERMUTED (R6 scheme):
// c = lane*4 + j + i*128  ->  idx = (i*4 + j)*32 + lane
__device__ float4 g_keff[B_ * CIN];

// ---------------------------------------------------------------------------
// Prologue: grid=(8,8), block=(64,8). 64-channel chunks, 8 j-slices of 16.
// ---------------------------------------------------------------------------
__global__ void build_keff_kernel(const float* __restrict__ w,
                                  const float* __restrict__ affine_w,
                                  const float* __restrict__ affine_b,
                                  const float* __restrict__ k2d)
{
    const int b  = blockIdx.x;
    const int c  = blockIdx.y * 64 + threadIdx.x;
    const int js = threadIdx.y;                    // 0..7

    __shared__ float ws[WDIM];
    __shared__ float part[7][64];

    const int tid = threadIdx.y * 64 + threadIdx.x;
    if (tid < WDIM) ws[tid] = w[b * WDIM + tid];
    __syncthreads();

    float s = 0.f;
    const int j0 = js * 16;
    #pragma unroll
    for (int j = j0; j < j0 + 16; j++)
        s = fmaf(ws[j], affine_w[j * CIN + c], s);

    if (js > 0) part[js - 1][threadIdx.x] = s;
    __syncthreads();

    if (js == 0) {
        #pragma unroll
        for (int q = 0; q < 7; q++) s += part[q][threadIdx.x];
        s = (s + affine_b[c]) * INV_SQRT_CIN;
        float4 kk = *reinterpret_cast<const float4*>(k2d + c * COUT);
        float4 o;
        o.x = s * kk.x; o.y = s * kk.y; o.z = s * kk.z; o.w = s * kk.w;
        // R6 permutation
        const int i = c >> 7, r = c & 127, lane = r >> 2, jj = r & 3;
        g_keff[b * CIN + (i * 4 + jj) * 32 + lane] = o;
    }
}

// packed pair reduction: two independent sums, one shuffle
__device__ __forceinline__ float pairstep(float a, float b, bool lo, int off)
{
    float send = lo ? b : a;
    float recv = __shfl_xor_sync(0xffffffffu, send, off);
    return (lo ? a : b) + recv;
}

// ---------------------------------------------------------------------------
// Main: grid=(74, 8), block=256 (8 warps), 4 CTAs/SM — one wave.
// Warp: 2 px per unit, rotated loop (loads for u+1 before reduce of u).
// ---------------------------------------------------------------------------
__global__ void __launch_bounds__(256, 4)
torgb_main_kernel(const float* __restrict__ x,
                  const float* __restrict__ bias,
                  float* __restrict__ out)
{
    const int b    = blockIdx.y;
    const int warp = threadIdx.x >> 5;
    const int lane = threadIdx.x & 31;

    __shared__ float4 kws[CIN];   // 8 KB

    {
        const float4* gk = g_keff + b * CIN;
        kws[threadIdx.x]       = gk[threadIdx.x];
        kws[threadIdx.x + 256] = gk[threadIdx.x + 256];
    }
    __syncthreads();

    const float4* kwl = kws + lane;

    // final packed-reduce slots (R2/R6-verified):
    // lanes with (lane&3)==0 store pixel p_off=bit4, output o_idx.
    const int   p_off  = (lane >> 4) & 1;
    const int   o_idx  = (((lane >> 2) & 1) << 1) | ((lane >> 3) & 1);
    const bool  storer = (lane & 3) == 0;
    const float mybias = bias[o_idx];
    const bool  lo16 = lane < 16;
    const bool  lo8  = (lane & 8) == 0;
    const bool  lo4  = (lane & 4) == 0;

    const long long px0 = (long long)b * PIX + (long long)blockIdx.x * UNIT_PX + warp * 2;
    const float4* xp = reinterpret_cast<const float4*>(x + px0 * CIN) + lane;
    float*        op = out + px0 * COUT + p_off * COUT + o_idx;

    const long long xstep = (long long)GRID_X * UNIT_PX * (CIN / 4);
    const long long ostep = (long long)GRID_X * UNIT_PX * COUT;

    // ---- preload unit blockIdx.x ----
    float4 a[4], c4[4];
    #pragma unroll
    for (int i = 0; i < 4; i++) a[i]  = __ldcs(xp + i * 32);
    #pragma unroll
    for (int i = 0; i < 4; i++) c4[i] = __ldcs(xp + 128 + i * 32);

    int u = blockIdx.x;
    #pragma unroll 1
    while (true) {
        // ---- FMA phase: consume a/c4 into v0..v7 ----
        float v0 = 0.f, v1 = 0.f, v2 = 0.f, v3 = 0.f;
        float v4 = 0.f, v5 = 0.f, v6 = 0.f, v7 = 0.f;

        #pragma unroll
        for (int i = 0; i < 4; i++) {
            const float av[4] = {a[i].x,  a[i].y,  a[i].z,  a[i].w};
            const float cv[4] = {c4[i].x, c4[i].y, c4[i].z, c4[i].w};
            #pragma unroll
            for (int j = 0; j < 4; j++) {
                const float4 k = kwl[(i * 4 + j) * 32];   // LDS.128, imm offset
                v0 = fmaf(av[j], k.x, v0);
                v1 = fmaf(av[j], k.y, v1);
                v2 = fmaf(av[j], k.z, v2);
                v3 = fmaf(av[j], k.w, v3);
                v4 = fmaf(cv[j], k.x, v4);
                v5 = fmaf(cv[j], k.y, v5);
                v6 = fmaf(cv[j], k.z, v6);
                v7 = fmaf(cv[j], k.w, v7);
            }
        }

        // ---- ROTATION: issue next unit's loads BEFORE the reduce chain ----
        const bool more = (u + GRID_X) < UNITS_PER_BATCH;
        xp += xstep;
        if (more) {
            #pragma unroll
            for (int i = 0; i < 4; i++) a[i]  = __ldcs(xp + i * 32);
            #pragma unroll
            for (int i = 0; i < 4; i++) c4[i] = __ldcs(xp + 128 + i * 32);
        }

        // ---- packed butterfly: 8 sums in 9 shuffles ----
        float r0 = pairstep(v0, v4, lo16, 16);
        float r1 = pairstep(v1, v5, lo16, 16);
        float r2 = pairstep(v2, v6, lo16, 16);
        float r3 = pairstep(v3, v7, lo16, 16);

        float s0 = pairstep(r0, r1, lo8, 8);
        float s1 = pairstep(r2, r3, lo8, 8);

        float t  = pairstep(s0, s1, lo4, 4);
        t += __shfl_xor_sync(0xffffffffu, t, 2);
        t += __shfl_xor_sync(0xffffffffu, t, 1);

        if (storer)
            *op = tanhf(t + mybias);

        if (!more) break;
        op += ostep;
        u  += GRID_X;
    }
}

// ---------------------------------------------------------------------------
// inputs: x[8,128,128,512], w[8,128], affine_w[128,512], affine_b[512],
//         kernel[1,1,512,4], bias[4]  -> out[8,128,128,4] f32
// ---------------------------------------------------------------------------
extern "C" void kernel_launch(void* const* d_in, const int* in_sizes, int n_in,
                              void* d_out, int out_size)
{
    const float* x        = (const float*)d_in[0];
    const float* w        = (const float*)d_in[1];
    const float* affine_w = (const float*)d_in[2];
    const float* affine_b = (const float*)d_in[3];
    const float* k2d      = (const float*)d_in[4];
    const float* bias     = (const float*)d_in[5];
    float*       out      = (float*)d_out;

    dim3 pgrid(B_, 8), pblock(64, 8);
    build_keff_kernel<<<pgrid, pblock>>>(w, affine_w, affine_b, k2d);

    dim3 grid(GRID_X, B_);
    torgb_main_kernel<<<grid, 256>>>(x, bias, out);
}

// round 10
// speedup vs baseline: 1.4427x; 1.0447x over previous
#include <cuda_runtime.h>
#include <math.h>

// ---------------------------------------------------------------------------
// ToRGB: out = tanh( (x * s[b]) @ k2d + bias ),  s = (w@affine_w + affine_b)/sqrt(512)
// Fold: keff[b,c,o] = s[b,c] * k2d[c,o]
// Main: R6 2-px body, math packed as fma.rn.f32x2 + tanh.approx.f32,
// persistent single-wave grid (74 x 8 = 592 CTAs).
// ---------------------------------------------------------------------------

#define B_    8
#define CIN   512
#define WDIM  128
#define COUT  4
#define PIX   (128*128)
#define INV_SQRT_CIN 0.04419417382415922f

#define GRID_X          74               // 74*8 = 592 = 148 SMs * 4 CTAs
#define UNIT_PX         16               // 8 warps * 2 px
#define UNITS_PER_BATCH (PIX / UNIT_PX)  // 1024

typedef unsigned long long u64;

// folded per-batch kernel, PERMUTED (R6 scheme):
// c = lane*4 + j + i*128  ->  idx = (i*4 + j)*32 + lane
__device__ float4 g_keff[B_ * CIN];

// ---------------------------------------------------------------------------
// Prologue: grid=(8,8), block=(64,8). 64-channel chunks, 8 j-slices of 16.
// ---------------------------------------------------------------------------
__global__ void build_keff_kernel(const float* __restrict__ w,
                                  const float* __restrict__ affine_w,
                                  const float* __restrict__ affine_b,
                                  const float* __restrict__ k2d)
{
    const int b  = blockIdx.x;
    const int c  = blockIdx.y * 64 + threadIdx.x;
    const int js = threadIdx.y;                    // 0..7

    __shared__ float ws[WDIM];
    __shared__ float part[7][64];

    const int tid = threadIdx.y * 64 + threadIdx.x;
    if (tid < WDIM) ws[tid] = w[b * WDIM + tid];
    __syncthreads();

    float s = 0.f;
    const int j0 = js * 16;
    #pragma unroll
    for (int j = j0; j < j0 + 16; j++)
        s = fmaf(ws[j], affine_w[j * CIN + c], s);

    if (js > 0) part[js - 1][threadIdx.x] = s;
    __syncthreads();

    if (js == 0) {
        #pragma unroll
        for (int q = 0; q < 7; q++) s += part[q][threadIdx.x];
        s = (s + affine_b[c]) * INV_SQRT_CIN;
        float4 kk = *reinterpret_cast<const float4*>(k2d + c * COUT);
        float4 o;
        o.x = s * kk.x; o.y = s * kk.y; o.z = s * kk.z; o.w = s * kk.w;
        const int i = c >> 7, r = c & 127, lane = r >> 2, jj = r & 3;
        g_keff[b * CIN + (i * 4 + jj) * 32 + lane] = o;
    }
}

// ---------------------------------------------------------------------------
// f32x2 packed math helpers (sm_103a)
// ---------------------------------------------------------------------------
__device__ __forceinline__ u64 pack_f32x2(float lo, float hi) {
    u64 r;
    asm("mov.b64 %0, {%1, %2};" : "=l"(r) : "f"(lo), "f"(hi));
    return r;
}
__device__ __forceinline__ void unpack_f32x2(float& lo, float& hi, u64 v) {
    asm("mov.b64 {%0, %1}, %2;" : "=f"(lo), "=f"(hi) : "l"(v));
}
__device__ __forceinline__ u64 fma_f32x2(u64 a, u64 b, u64 c) {
    u64 d;
    asm("fma.rn.f32x2 %0, %1, %2, %3;" : "=l"(d) : "l"(a), "l"(b), "l"(c));
    return d;
}
__device__ __forceinline__ float tanh_fast(float x) {
    float r;
    asm("tanh.approx.f32 %0, %1;" : "=f"(r) : "f"(x));
    return r;
}

// packed pair reduction: two independent sums, one shuffle
__device__ __forceinline__ float pairstep(float a, float b, bool lo, int off)
{
    float send = lo ? b : a;
    float recv = __shfl_xor_sync(0xffffffffu, send, off);
    return (lo ? a : b) + recv;
}

// ---------------------------------------------------------------------------
// Main: grid=(74, 8), block=256 (8 warps), 4 CTAs/SM — one wave.
// Warp: 2 px per unit; f32x2-packed FMA; 9-shuffle packed reduce.
// ---------------------------------------------------------------------------
__global__ void __launch_bounds__(256, 4)
torgb_main_kernel(const float* __restrict__ x,
                  const float* __restrict__ bias,
                  float* __restrict__ out)
{
    const int b    = blockIdx.y;
    const int warp = threadIdx.x >> 5;
    const int lane = threadIdx.x & 31;

    __shared__ __align__(16) float4 kws[CIN];   // 8 KB

    {
        const float4* gk = g_keff + b * CIN;
        kws[threadIdx.x]       = gk[threadIdx.x];
        kws[threadIdx.x + 256] = gk[threadIdx.x + 256];
    }
    __syncthreads();

    // keff as packed pairs: kwl2[idx].x = (k.x,k.y), .y = (k.z,k.w)
    const ulonglong2* kwl2 = reinterpret_cast<const ulonglong2*>(kws) + lane;

    // final packed-reduce slots (R2/R6-verified):
    // lanes with (lane&3)==0 store pixel p_off=bit4, output o_idx.
    const int   p_off  = (lane >> 4) & 1;
    const int   o_idx  = (((lane >> 2) & 1) << 1) | ((lane >> 3) & 1);
    const bool  storer = (lane & 3) == 0;
    const float mybias = bias[o_idx];
    const bool  lo16 = lane < 16;
    const bool  lo8  = (lane & 8) == 0;
    const bool  lo4  = (lane & 4) == 0;

    const long long px0 = (long long)b * PIX + (long long)blockIdx.x * UNIT_PX + warp * 2;
    const float4* xp = reinterpret_cast<const float4*>(x + px0 * CIN) + lane;
    float*        op = out + px0 * COUT + p_off * COUT + o_idx;

    const long long xstep = (long long)GRID_X * UNIT_PX * (CIN / 4);
    const long long ostep = (long long)GRID_X * UNIT_PX * COUT;

    #pragma unroll 1
    for (int u = blockIdx.x; u < UNITS_PER_BATCH; u += GRID_X) {
        // ---- 2 pixels: 8 independent LDG.128 ----
        float4 a[4], c4[4];
        #pragma unroll
        for (int i = 0; i < 4; i++) a[i]  = __ldcs(xp + i * 32);
        #pragma unroll
        for (int i = 0; i < 4; i++) c4[i] = __ldcs(xp + 128 + i * 32);

        // packed accumulators: p0a=(v0,v1) p0b=(v2,v3) p1a=(v4,v5) p1b=(v6,v7)
        u64 p0a = 0ull, p0b = 0ull, p1a = 0ull, p1b = 0ull;

        #pragma unroll
        for (int i = 0; i < 4; i++) {
            const float av[4] = {a[i].x,  a[i].y,  a[i].z,  a[i].w};
            const float cv[4] = {c4[i].x, c4[i].y, c4[i].z, c4[i].w};
            u64 ap[4], cp[4];
            #pragma unroll
            for (int j = 0; j < 4; j++) {
                ap[j] = pack_f32x2(av[j], av[j]);
                cp[j] = pack_f32x2(cv[j], cv[j]);
            }
            #pragma unroll
            for (int j = 0; j < 4; j++) {
                const ulonglong2 kk = kwl2[(i * 4 + j) * 32];   // LDS.128
                p0a = fma_f32x2(ap[j], kk.x, p0a);
                p0b = fma_f32x2(ap[j], kk.y, p0b);
                p1a = fma_f32x2(cp[j], kk.x, p1a);
                p1b = fma_f32x2(cp[j], kk.y, p1b);
            }
        }

        float v0, v1, v2, v3, v4, v5, v6, v7;
        unpack_f32x2(v0, v1, p0a);
        unpack_f32x2(v2, v3, p0b);
        unpack_f32x2(v4, v5, p1a);
        unpack_f32x2(v6, v7, p1b);

        // ---- packed butterfly: 8 sums in 9 shuffles (R6-verified) ----
        float r0 = pairstep(v0, v4, lo16, 16);
        float r1 = pairstep(v1, v5, lo16, 16);
        float r2 = pairstep(v2, v6, lo16, 16);
        float r3 = pairstep(v3, v7, lo16, 16);

        float s0 = pairstep(r0, r1, lo8, 8);
        float s1 = pairstep(r2, r3, lo8, 8);

        float t  = pairstep(s0, s1, lo4, 4);
        t += __shfl_xor_sync(0xffffffffu, t, 2);
        t += __shfl_xor_sync(0xffffffffu, t, 1);

        if (storer)
            *op = tanh_fast(t + mybias);

        xp += xstep;
        op += ostep;
    }
}

// ---------------------------------------------------------------------------
// inputs: x[8,128,128,512], w[8,128], affine_w[128,512], affine_b[512],
//         kernel[1,1,512,4], bias[4]  -> out[8,128,128,4] f32
// ---------------------------------------------------------------------------
extern "C" void kernel_launch(void* const* d_in, const int* in_sizes, int n_in,
                              void* d_out, int out_size)
{
    const float* x        = (const float*)d_in[0];
    const float* w        = (const float*)d_in[1];
    const float* affine_w = (const float*)d_in[2];
    const float* affine_b = (const float*)d_in[3];
    const float* k2d      = (const float*)d_in[4];
    const float* bias     = (const float*)d_in[5];
    float*       out      = (float*)d_out;

    dim3 pgrid(B_, 8), pblock(64, 8);
    build_keff_kernel<<<pgrid, pblock>>>(w, affine_w, affine_b, k2d);

    dim3 grid(GRID_X, B_);
    torgb_main_kernel<<<grid, 256>>>(x, bias, out);
}